// round 16
// baseline (speedup 1.0000x reference)
#include <cuda_runtime.h>
#include <cuda_fp16.h>
#include <cstdint>

// VanillaRNN on GB300 — Round 15: producer/consumer warp specialization.
//
//   new_state = ReLU(X@W_in^T + state@W_rec^T + b_in + b_rec)  [8192,4096]
//   out       = ReLU(new_state@W_out^T + b_out)                [8192,1024]
// d_out = (out, new_state) fp32; inputs converted to fp16 RN each call.
//
// GEMM: BM=128, BN=256, BK=64. 544 threads = 16 consumer warps (4x4, warp
// tile 32x64, R13 layout) + 1 producer warp issuing ALL cp.async (3-stage
// ring). Stage handoff via named barriers (ids 1-6):
//   READY[s]: producer bar.arrive (after cp.async.wait_group), consumers bar.sync
//   FREE[s]:  consumers bar.arrive (after compute), producer bar.sync
// Producer runs 2 stages ahead -> consumers' bar.sync READY usually passes
// immediately, so warps de-phase instead of executing in lockstep (the
// R12/R13 limiter). No __syncthreads in the GEMM (barrier 0 untouched).

#define BM 128
#define BN 256
#define BK 64
#define STAGES 3
#define THREADS 544
#define NWARPC 16
#define SROWH 72                            // halves per smem row (64+8 pad)=144B
#define A_HALVES (BM * SROWH)               // 9216
#define B_HALVES (BN * SROWH)               // 18432
#define STAGE_BYTES ((A_HALVES + B_HALVES) * 2)  // 55296
#define SMEM_BYTES  (STAGES * STAGE_BYTES)       // 165888

// ---- fp16 scratch (static device globals; allowed scratch mechanism) ----
__device__ __align__(16) __half g_hX[8192 * 1024];
__device__ __align__(16) __half g_hState[8192 * 4096];
__device__ __align__(16) __half g_hWin[4096 * 1024];
__device__ __align__(16) __half g_hWrec[4096 * 4096];
__device__ __align__(16) __half g_hWout[1024 * 4096];
__device__ __align__(16) __half g_hNew[8192 * 4096];

__device__ __forceinline__ uint32_t s2u(const void* p) {
    uint32_t a;
    asm("{ .reg .u64 t; cvta.to.shared.u64 t, %1; cvt.u32.u64 %0, t; }" : "=r"(a) : "l"(p));
    return a;
}

#define CP16(dst, src) \
    asm volatile("cp.async.cg.shared.global [%0], [%1], 16;" :: "r"(dst), "l"(src))
#define CP_COMMIT() asm volatile("cp.async.commit_group;" ::: "memory")
#define CP_WAIT(N)  asm volatile("cp.async.wait_group %0;" :: "n"(N) : "memory")

#define BAR_SYNC(id)   asm volatile("bar.sync %0, %1;"   :: "r"(id), "r"(THREADS) : "memory")
#define BAR_ARRIVE(id) asm volatile("bar.arrive %0, %1;" :: "r"(id), "r"(THREADS) : "memory")
#define BAR_READY(s) (1 + (s))
#define BAR_FREE(s)  (4 + (s))

#define LDSM4(r0, r1, r2, r3, addr)                                            \
    asm volatile("ldmatrix.sync.aligned.m8n8.x4.shared.b16 {%0,%1,%2,%3}, [%4];" \
                 : "=r"(r0), "=r"(r1), "=r"(r2), "=r"(r3) : "r"(addr))

#define MMA_F16(ac, a0, a1, a2, a3, b0, b1)                                    \
    asm volatile(                                                              \
        "mma.sync.aligned.m16n8k16.row.col.f32.f16.f16.f32 "                   \
        "{%0,%1,%2,%3}, {%4,%5,%6,%7}, {%8,%9}, {%0,%1,%2,%3};"                \
        : "+f"((ac)[0]), "+f"((ac)[1]), "+f"((ac)[2]), "+f"((ac)[3])           \
        : "r"(a0), "r"(a1), "r"(a2), "r"(a3), "r"(b0), "r"(b1))

// ---- fp32 -> fp16 RN converter ----
__global__ void __launch_bounds__(256) f2h_kernel(const float4* __restrict__ src,
                                                  __half* __restrict__ dst, int n4)
{
    int i = blockIdx.x * blockDim.x + threadIdx.x;
    if (i < n4) {
        float4 v = src[i];
        __half2 h0 = __floats2half2_rn(v.x, v.y);
        __half2 h1 = __floats2half2_rn(v.z, v.w);
        uint2 pk;
        pk.x = *(uint32_t*)&h0;
        pk.y = *(uint32_t*)&h1;
        *(uint2*)(dst + 4 * (size_t)i) = pk;
    }
}

__global__ void __launch_bounds__(THREADS, 1) rnn_gemm_h(
    const __half* __restrict__ A1, int lda1,
    const __half* __restrict__ B1, int ldb1, int n1,
    const __half* __restrict__ A2, int lda2,
    const __half* __restrict__ B2, int ldb2, int n2,
    const float* __restrict__ bias1, const float* __restrict__ bias2,
    float* __restrict__ C, int ldc, __half* __restrict__ hC)
{
    extern __shared__ __align__(16) char smem[];
    const uint32_t sbase = s2u(smem);

    const int tid  = threadIdx.x;
    const int warp = tid >> 5;
    const int lane = tid & 31;
    const int rowBase = blockIdx.y * BM;
    const int colBase = blockIdx.x * BN;
    const int niters  = n1 + n2;

    if (warp == NWARPC) {
        // ================= producer warp =================
        const int lr = lane >> 3;          // 0..3 row group within 4-row step
        const int ch = lane & 7;           // 16B chunk within 128B row
#pragma unroll 1
        for (int j = 0; j < niters; ++j) {
            const int s = j % STAGES;
            if (j >= STAGES) BAR_SYNC(BAR_FREE(s));

            const __half* Ab; const __half* Bb; int lda, ldb, ko;
            if (j < n1) { Ab = A1; Bb = B1; lda = lda1; ldb = ldb1; ko = j * BK; }
            else        { Ab = A2; Bb = B2; lda = lda2; ldb = ldb2; ko = (j - n1) * BK; }
            const uint32_t base = sbase + s * STAGE_BYTES;

            // A: 128 rows, 8 chunks/row = 1024 chunks; 32 per lane
            {
                const __half* g = Ab + (size_t)(rowBase + lr) * lda + ko + ch * 8;
                uint32_t st = base + lr * (SROWH * 2) + ch * 16;
#pragma unroll 8
                for (int kk = 0; kk < 32; kk++) {
                    CP16(st, g);
                    g  += (size_t)4 * lda;
                    st += 4 * (SROWH * 2);
                }
            }
            // B: 256 rows, 8 chunks/row = 2048 chunks; 64 per lane
            {
                const __half* g = Bb + (size_t)(colBase + lr) * ldb + ko + ch * 8;
                uint32_t st = base + A_HALVES * 2 + lr * (SROWH * 2) + ch * 16;
#pragma unroll 8
                for (int kk = 0; kk < 64; kk++) {
                    CP16(st, g);
                    g  += (size_t)4 * ldb;
                    st += 4 * (SROWH * 2);
                }
            }
            CP_COMMIT();
            if (j >= 2) { CP_WAIT(2); BAR_ARRIVE(BAR_READY((j - 2) % STAGES)); }
        }
        // drain the last two groups
        CP_WAIT(1); BAR_ARRIVE(BAR_READY((niters - 2) % STAGES));
        CP_WAIT(0); BAR_ARRIVE(BAR_READY((niters - 1) % STAGES));
        return;
    }

    // ================= consumer warps (R13 layout) =================
    const int tg = lane & 3;
    const int g  = lane >> 2;
    const int wm = warp >> 2;   // 0..3, rows wm*32..+32
    const int wn = warp & 3;    // 0..3, cols wn*64..+64
    const uint32_t laneOff = (uint32_t)(lane & 15) * (SROWH * 2) + ((lane >> 4) << 4);

    float acc[2][8][4];
#pragma unroll
    for (int i = 0; i < 2; i++)
#pragma unroll
        for (int j = 0; j < 8; j++)
#pragma unroll
            for (int v = 0; v < 4; v++) acc[i][j][v] = 0.0f;

#pragma unroll 1
    for (int it = 0; it < niters; ++it) {
        const int s = it % STAGES;
        BAR_SYNC(BAR_READY(s));

        const uint32_t stA = sbase + s * STAGE_BYTES
                           + (uint32_t)(wm * 32) * (SROWH * 2);
        const uint32_t stB = sbase + s * STAGE_BYTES + A_HALVES * 2
                           + (uint32_t)(wn * 64) * (SROWH * 2);

#pragma unroll
        for (int ks = 0; ks < 4; ks++) {        // four k16 steps per BK=64
            const uint32_t ko = (uint32_t)(ks * 32) + laneOff;
            uint32_t fa[8], fb[16];
#pragma unroll
            for (int i = 0; i < 2; i++)
                LDSM4(fa[4 * i], fa[4 * i + 1], fa[4 * i + 2], fa[4 * i + 3],
                      stA + ko + (uint32_t)(i * 16) * (SROWH * 2));
#pragma unroll
            for (int jp = 0; jp < 4; jp++)
                LDSM4(fb[4 * jp], fb[4 * jp + 1], fb[4 * jp + 2], fb[4 * jp + 3],
                      stB + ko + (uint32_t)(jp * 16) * (SROWH * 2));

#pragma unroll
            for (int i = 0; i < 2; i++)
#pragma unroll
                for (int j = 0; j < 8; j++) {
                    const int jp = j >> 1, jo = j & 1;
                    MMA_F16(acc[i][j],
                            fa[4 * i], fa[4 * i + 1], fa[4 * i + 2], fa[4 * i + 3],
                            fb[4 * jp + jo], fb[4 * jp + 2 + jo]);
                }
        }
        BAR_ARRIVE(BAR_FREE(s));
    }

    // ---- epilogue: bias + ReLU; fp32 store (+ optional fp16 mirror) ----
    float2 bv[8];
#pragma unroll
    for (int j = 0; j < 8; j++) {
        const int c = colBase + wn * 64 + j * 8 + 2 * tg;
        float2 b = *(const float2*)(bias1 + c);
        if (bias2) {
            float2 b2 = *(const float2*)(bias2 + c);
            b.x += b2.x; b.y += b2.y;
        }
        bv[j] = b;
    }
#pragma unroll
    for (int i = 0; i < 2; i++) {
        const int r0 = rowBase + wm * 32 + i * 16 + g;
#pragma unroll
        for (int j = 0; j < 8; j++) {
            const int c = colBase + wn * 64 + j * 8 + 2 * tg;
            float2 v0, v1;
            v0.x = fmaxf(acc[i][j][0] + bv[j].x, 0.0f);
            v0.y = fmaxf(acc[i][j][1] + bv[j].y, 0.0f);
            v1.x = fmaxf(acc[i][j][2] + bv[j].x, 0.0f);
            v1.y = fmaxf(acc[i][j][3] + bv[j].y, 0.0f);
            *(float2*)&C[(size_t)r0 * ldc + c]       = v0;
            *(float2*)&C[(size_t)(r0 + 8) * ldc + c] = v1;
            if (hC) {
                __half2 h0 = __floats2half2_rn(v0.x, v0.y);
                __half2 h1 = __floats2half2_rn(v1.x, v1.y);
                *(__half2*)(hC + (size_t)r0 * ldc + c)       = h0;
                *(__half2*)(hC + (size_t)(r0 + 8) * ldc + c) = h1;
            }
        }
    }
}

// force eager module load (incl. device globals) before harness checkpoints
namespace {
struct EagerInit {
    EagerInit() { void* p = nullptr; cudaGetSymbolAddress(&p, g_hX); }
};
EagerInit s_eager;
}

extern "C" void kernel_launch(void* const* d_in, const int* in_sizes, int n_in,
                              void* d_out, int out_size)
{
    (void)in_sizes; (void)n_in; (void)out_size;
    const int B_ = 8192, DIN = 1024, H_ = 4096, DO_ = 1024;

    const float* X     = (const float*)d_in[0];
    const float* state = (const float*)d_in[1];
    const float* W_in  = (const float*)d_in[2];
    const float* b_in  = (const float*)d_in[3];
    const float* W_rec = (const float*)d_in[4];
    const float* b_rec = (const float*)d_in[5];
    const float* W_out = (const float*)d_in[6];
    const float* b_out = (const float*)d_in[7];

    float* out       = (float*)d_out;                     // [B, D_OUT]
    float* new_state = (float*)d_out + (size_t)B_ * DO_;  // [B, H]

    static __half *hX, *hState, *hWin, *hWrec, *hWout, *hNew;
    static int inited = 0;
    if (!inited) {
        cudaFuncSetAttribute(rnn_gemm_h,
                             cudaFuncAttributeMaxDynamicSharedMemorySize, SMEM_BYTES);
        cudaGetSymbolAddress((void**)&hX,     g_hX);
        cudaGetSymbolAddress((void**)&hState, g_hState);
        cudaGetSymbolAddress((void**)&hWin,   g_hWin);
        cudaGetSymbolAddress((void**)&hWrec,  g_hWrec);
        cudaGetSymbolAddress((void**)&hWout,  g_hWout);
        cudaGetSymbolAddress((void**)&hNew,   g_hNew);
        inited = 1;
    }

    // ---- fp32 -> fp16 conversions ----
    auto conv = [&](const float* src, __half* dst, size_t n) {
        int n4 = (int)(n / 4);
        f2h_kernel<<<(n4 + 255) / 256, 256>>>((const float4*)src, dst, n4);
    };
    conv(X,     hX,     (size_t)B_ * DIN);
    conv(state, hState, (size_t)B_ * H_);
    conv(W_in,  hWin,   (size_t)H_ * DIN);
    conv(W_rec, hWrec,  (size_t)H_ * H_);
    conv(W_out, hWout,  (size_t)DO_ * H_);

    // GEMM1+2 fused along K: new_state = ReLU(X@W_in^T + state@W_rec^T + b)
    {
        dim3 grid(H_ / BN, B_ / BM);   // (16, 64)
        rnn_gemm_h<<<grid, THREADS, SMEM_BYTES>>>(
            hX, DIN, hWin, DIN, DIN / BK,
            hState, H_, hWrec, H_, H_ / BK,
            b_in, b_rec, new_state, H_, hNew);
    }
    // GEMM3: out = ReLU(new_state@W_out^T + b_out)
    {
        dim3 grid(DO_ / BN, B_ / BM);  // (4, 64)
        rnn_gemm_h<<<grid, THREADS, SMEM_BYTES>>>(
            hNew, H_, hWout, H_, H_ / BK,
            nullptr, 0, nullptr, 0, 0,
            b_out, nullptr, out, DO_, nullptr);
    }
}